// round 2
// baseline (speedup 1.0000x reference)
#include <cuda_runtime.h>
#include <cstdint>

#define B_  4096
#define T_  2048
#define HH  32
#define NGRP (B_ / 4)          // 1024 groups of 4 sequences

// ---------------- device globals ----------------
__device__ int g_next;
__device__ int g_cnt[T_];
__device__ int g_order[B_];

// ---------------- helpers ----------------
__device__ __forceinline__ unsigned long long ffma2(unsigned long long a,
                                                    unsigned long long b,
                                                    unsigned long long c) {
    unsigned long long d;
    asm("fma.rn.f32x2 %0, %1, %2, %3;" : "=l"(d) : "l"(a), "l"(b), "l"(c));
    return d;
}
__device__ __forceinline__ unsigned long long pk2(float lo, float hi) {
    unsigned long long r;
    asm("mov.b64 %0, {%1, %2};" : "=l"(r) : "f"(lo), "f"(hi));
    return r;
}
__device__ __forceinline__ float2 unpk(unsigned long long v) {
    float2 r;
    asm("mov.b64 {%0, %1}, %2;" : "=f"(r.x), "=f"(r.y) : "l"(v));
    return r;
}
__device__ __forceinline__ float ex2a(float x) {
    float r; asm("ex2.approx.f32 %0, %1;" : "=f"(r) : "f"(x)); return r;
}
__device__ __forceinline__ float rcpa(float x) {
    float r; asm("rcp.approx.f32 %0, %1;" : "=f"(r) : "f"(x)); return r;
}
#define LOG2E 1.4426950408889634f
// pre-scaled sigmoid: input already multiplied by -LOG2E
__device__ __forceinline__ float sig_pre(float xs) {
    return rcpa(1.0f + ex2a(xs));
}
// pre-scaled tanh: input already multiplied by 2*LOG2E
__device__ __forceinline__ float tanh_pre(float xs) {
    return fmaf(-2.0f, rcpa(1.0f + ex2a(xs)), 1.0f);
}
__device__ __forceinline__ float sig_f(float x) {
    return rcpa(1.0f + ex2a(-LOG2E * x));
}

// ---------------- counting sort by descending length ----------------
__global__ void k_zero() {
    int i = blockIdx.x * blockDim.x + threadIdx.x;
    if (i < T_) g_cnt[i] = 0;
    if (i == 0) g_next = 0;
}
__global__ void k_hist(const int* __restrict__ lengths) {
    int b = blockIdx.x * blockDim.x + threadIdx.x;
    if (b < B_) atomicAdd(&g_cnt[T_ - lengths[b]], 1);
}
__global__ void k_scan() {
    __shared__ int ps[1024];
    int tid = threadIdx.x;
    int a = g_cnt[2 * tid], b = g_cnt[2 * tid + 1];
    int s = a + b;
    ps[tid] = s;
    __syncthreads();
    for (int d = 1; d < 1024; d <<= 1) {
        int v = (tid >= d) ? ps[tid - d] : 0;
        __syncthreads();
        ps[tid] += v;
        __syncthreads();
    }
    int incl = ps[tid];
    int excl = incl - s;
    g_cnt[2 * tid]     = excl;
    g_cnt[2 * tid + 1] = excl + a;
}
__global__ void k_scatter(const int* __restrict__ lengths) {
    int b = blockIdx.x * blockDim.x + threadIdx.x;
    if (b < B_) {
        int pos = atomicAdd(&g_cnt[T_ - lengths[b]], 1);
        g_order[pos] = b;
    }
}

// ---------------- main kernel: one warp == 4 sequences ----------------
// lane l owns element l of each h/c; gate rows {l,32+l,64+l,96+l}.
// Weights pre-scaled: i/f/o rows by -LOG2E (sigmoid), g row by +2*LOG2E (tanh).
__global__ __launch_bounds__(256, 2) void k_lstm(
    const float* __restrict__ x,      const int*   __restrict__ lengths,
    const float* __restrict__ w_ih,   const float* __restrict__ w_hh,
    const float* __restrict__ b_ih,   const float* __restrict__ b_hh,
    const float* __restrict__ fc_w,   const float* __restrict__ fc_b,
    const float* __restrict__ fc2_w,  const float* __restrict__ fc2_b,
    float* __restrict__ out)
{
    // Wp[(g*8+q)*32 + l] = float4 of scaled w_hh[32g+l][4q..4q+3]
    __shared__ __align__(16) float4 Wp[1024];                  // 16 KB
    __shared__ __align__(16) float  hs[2][8][4][HH];           // 8 KB

    const int tid  = threadIdx.x;
    const int lane = tid & 31;
    const int wrp  = tid >> 5;

    for (int e = tid; e < 1024; e += blockDim.x) {
        int g = e >> 8, q = (e >> 5) & 7, l = e & 31;
        float sc = (g == 2) ? (2.0f * LOG2E) : (-LOG2E);
        const float* wr = w_hh + (32 * g + l) * 32 + 4 * q;
        Wp[e] = make_float4(wr[0] * sc, wr[1] * sc, wr[2] * sc, wr[3] * sc);
    }
    __syncthreads();

    float wih[4], bias[4];
#pragma unroll
    for (int g = 0; g < 4; g++) {
        int j = 32 * g + lane;
        float sc = (g == 2) ? (2.0f * LOG2E) : (-LOG2E);
        wih[g]  = w_ih[j] * sc;
        bias[g] = (b_ih[j] + b_hh[j]) * sc;
    }
    const ulonglong2* WpU = reinterpret_cast<const ulonglong2*>(Wp) + lane;

    for (;;) {
        int task = 0;
        if (lane == 0) task = atomicAdd(&g_next, 1);
        task = __shfl_sync(0xffffffffu, task, 0);
        if (task >= NGRP) break;

        int sid[4], len[4];
        const float* xp[4];
#pragma unroll
        for (int s = 0; s < 4; s++) {
            sid[s] = g_order[4 * task + s];
            len[s] = lengths[sid[s]];
            xp[s]  = x + (long)sid[s] * T_;
        }
        const int maxlen = len[0];   // descending sort => len[0] is max

        float c[4], hown[4], xt[4];
#pragma unroll
        for (int s = 0; s < 4; s++) {
            c[s] = 0.0f; hown[s] = 0.0f;
            hs[0][wrp][s][lane] = 0.0f;
            hs[1][wrp][s][lane] = 0.0f;
            xt[s] = __ldg(xp[s] + len[s] - 1);
        }
        __syncwarp();

        int pb = 0;
        for (int k = 0; k < maxlen; ++k) {
            float xn[4];
#pragma unroll
            for (int s = 0; s < 4; s++) {
                int ix = len[s] - 2 - k;
                xn[s] = (ix >= 0) ? __ldg(xp[s] + ix) : 0.0f;
            }

            const float* hb = &hs[pb][wrp][0][0];
            unsigned long long acc[4][4];
#pragma unroll
            for (int s = 0; s < 4; s++)
#pragma unroll
                for (int g = 0; g < 4; g++)
                    acc[s][g] = pk2(fmaf(xt[s], wih[g], bias[g]), 0.0f);

#pragma unroll
            for (int q = 0; q < 8; q++) {
                ulonglong2 w0 = WpU[(0 * 8 + q) * 32];
                ulonglong2 w1 = WpU[(1 * 8 + q) * 32];
                ulonglong2 w2 = WpU[(2 * 8 + q) * 32];
                ulonglong2 w3 = WpU[(3 * 8 + q) * 32];
#pragma unroll
                for (int s = 0; s < 4; s++) {
                    ulonglong2 h2 =
                        reinterpret_cast<const ulonglong2*>(hb + s * HH)[q];
                    acc[s][0] = ffma2(h2.x, w0.x, acc[s][0]);
                    acc[s][0] = ffma2(h2.y, w0.y, acc[s][0]);
                    acc[s][1] = ffma2(h2.x, w1.x, acc[s][1]);
                    acc[s][1] = ffma2(h2.y, w1.y, acc[s][1]);
                    acc[s][2] = ffma2(h2.x, w2.x, acc[s][2]);
                    acc[s][2] = ffma2(h2.y, w2.y, acc[s][2]);
                    acc[s][3] = ffma2(h2.x, w3.x, acc[s][3]);
                    acc[s][3] = ffma2(h2.y, w3.y, acc[s][3]);
                }
            }

            const int npb = pb ^ 1;
#pragma unroll
            for (int s = 0; s < 4; s++) {
                float2 a0 = unpk(acc[s][0]), a1 = unpk(acc[s][1]);
                float2 a2 = unpk(acc[s][2]), a3 = unpk(acc[s][3]);
                float iv = sig_pre(a0.x + a0.y);
                float fv = sig_pre(a1.x + a1.y);
                float gv = tanh_pre(a2.x + a2.y);
                float ov = sig_pre(a3.x + a3.y);
                float cn = fmaf(fv, c[s], iv * gv);
                float hn = ov * tanh_pre(2.0f * LOG2E * cn);
                if (k < len[s]) { c[s] = cn; hown[s] = hn; }
                hs[npb][wrp][s][lane] = hown[s];
            }
            pb = npb;
            __syncwarp();
#pragma unroll
            for (int s = 0; s < 4; s++) xt[s] = xn[s];
        }

        // ---- MLP head for the 4 sequences ----
#pragma unroll 1
        for (int s = 0; s < 4; s++) {
            const float* hf = hs[pb][wrp][s];
            float y0 = fc_b[lane];
            float y1 = fc_b[lane + 32];
#pragma unroll
            for (int kk = 0; kk < 32; kk++) {
                float hk = hf[kk];
                y0 = fmaf(hk, __ldg(fc_w + lane * 32 + kk),        y0);
                y1 = fmaf(hk, __ldg(fc_w + (lane + 32) * 32 + kk), y1);
            }
            float e0 = (y0 > 0.0f) ? y0 : (ex2a(LOG2E * y0) - 1.0f);
            float e1 = (y1 > 0.0f) ? y1 : (ex2a(LOG2E * y1) - 1.0f);
            float p  = fmaf(e0, __ldg(fc2_w + lane),
                            e1 * __ldg(fc2_w + lane + 32));
#pragma unroll
            for (int off = 16; off; off >>= 1)
                p += __shfl_xor_sync(0xffffffffu, p, off);
            if (lane == 0) out[sid[s]] = sig_f(p + fc2_b[0]);
        }
        __syncwarp();
    }
}

// ---------------- launch ----------------
extern "C" void kernel_launch(void* const* d_in, const int* in_sizes, int n_in,
                              void* d_out, int out_size)
{
    const float* x       = (const float*)d_in[0];
    const int*   lengths = (const int*)  d_in[1];
    const float* w_ih    = (const float*)d_in[2];
    const float* w_hh    = (const float*)d_in[3];
    const float* b_ih    = (const float*)d_in[4];
    const float* b_hh    = (const float*)d_in[5];
    const float* fc_w    = (const float*)d_in[6];
    const float* fc_b    = (const float*)d_in[7];
    const float* fc2_w   = (const float*)d_in[8];
    const float* fc2_b   = (const float*)d_in[9];
    float* out = (float*)d_out;

    k_zero<<<2, 1024>>>();
    k_hist<<<B_ / 256, 256>>>(lengths);
    k_scan<<<1, 1024>>>();
    k_scatter<<<B_ / 256, 256>>>(lengths);
    k_lstm<<<148 * 2, 256>>>(x, lengths, w_ih, w_hh, b_ih, b_hh,
                             fc_w, fc_b, fc2_w, fc2_b, out);
}

// round 3
// speedup vs baseline: 3.3060x; 3.3060x over previous
#include <cuda_runtime.h>
#include <cstdint>

#define B_  4096
#define T_  2048
#define HH  32
typedef unsigned long long ull;

// ---------------- device globals ----------------
__device__ int g_next;
__device__ int g_cnt[T_];
__device__ int g_order[B_];

// ---------------- helpers ----------------
__device__ __forceinline__ ull ffma2(ull a, ull b, ull c) {
    ull d;
    asm("fma.rn.f32x2 %0, %1, %2, %3;" : "=l"(d) : "l"(a), "l"(b), "l"(c));
    return d;
}
__device__ __forceinline__ ull pk2(float lo, float hi) {
    ull r;
    asm("mov.b64 %0, {%1, %2};" : "=l"(r) : "f"(lo), "f"(hi));
    return r;
}
__device__ __forceinline__ float2 unpk(ull v) {
    float2 r;
    asm("mov.b64 {%0, %1}, %2;" : "=f"(r.x), "=f"(r.y) : "l"(v));
    return r;
}
__device__ __forceinline__ float ex2a(float x) {
    float r; asm("ex2.approx.f32 %0, %1;" : "=f"(r) : "f"(x)); return r;
}
__device__ __forceinline__ float rcpa(float x) {
    float r; asm("rcp.approx.f32 %0, %1;" : "=f"(r) : "f"(x)); return r;
}
#define LOG2E 1.4426950408889634f
// pre-scaled sigmoid: argument already multiplied by -LOG2E
__device__ __forceinline__ float sig_pre(float xs) {
    return rcpa(1.0f + ex2a(xs));
}
// pre-scaled tanh: argument already multiplied by 2*LOG2E
__device__ __forceinline__ float tanh_pre(float xs) {
    return fmaf(-2.0f, rcpa(1.0f + ex2a(xs)), 1.0f);
}
__device__ __forceinline__ float sig_f(float x) {
    return rcpa(1.0f + ex2a(-LOG2E * x));
}

// ---------------- counting sort by descending length ----------------
__global__ void k_zero() {
    int i = blockIdx.x * blockDim.x + threadIdx.x;
    if (i < T_) g_cnt[i] = 0;
    if (i == 0) g_next = 0;
}
__global__ void k_hist(const int* __restrict__ lengths) {
    int b = blockIdx.x * blockDim.x + threadIdx.x;
    if (b < B_) atomicAdd(&g_cnt[T_ - lengths[b]], 1);
}
__global__ void k_scan() {
    __shared__ int ps[1024];
    int tid = threadIdx.x;
    int a = g_cnt[2 * tid], b = g_cnt[2 * tid + 1];
    int s = a + b;
    ps[tid] = s;
    __syncthreads();
    for (int d = 1; d < 1024; d <<= 1) {
        int v = (tid >= d) ? ps[tid - d] : 0;
        __syncthreads();
        ps[tid] += v;
        __syncthreads();
    }
    int incl = ps[tid];
    int excl = incl - s;
    g_cnt[2 * tid]     = excl;
    g_cnt[2 * tid + 1] = excl + a;
}
__global__ void k_scatter(const int* __restrict__ lengths) {
    int b = blockIdx.x * blockDim.x + threadIdx.x;
    if (b < B_) {
        int pos = atomicAdd(&g_cnt[T_ - lengths[b]], 1);
        g_order[pos] = b;
    }
}

// ---------------- main kernel: one warp == one sequence ----------------
// lane l owns h/c element l and gate rows {l, 32+l, 64+l, 96+l}.
// ALL recurrent weights live in registers (64 packed f32x2 per lane),
// pre-scaled: i/f/o rows by -LOG2E, g row by +2*LOG2E.
// Shared memory only carries the 32-float h vector (double-buffered).
__global__ __launch_bounds__(256, 1) void k_lstm(
    const float* __restrict__ x,      const int*   __restrict__ lengths,
    const float* __restrict__ w_ih,   const float* __restrict__ w_hh,
    const float* __restrict__ b_ih,   const float* __restrict__ b_hh,
    const float* __restrict__ fc_w,   const float* __restrict__ fc_b,
    const float* __restrict__ fc2_w,  const float* __restrict__ fc2_b,
    float* __restrict__ out)
{
    __shared__ __align__(16) float hs[2][8][HH];    // 2 KB: h per warp, 2 bufs

    const int lane = threadIdx.x & 31;
    const int wrp  = threadIdx.x >> 5;

    // ---- load recurrent weights into registers (pre-scaled) ----
    ull w[4][16];
    float wih[4], bias[4];
#pragma unroll
    for (int g = 0; g < 4; g++) {
        const float sc = (g == 2) ? (2.0f * LOG2E) : (-LOG2E);
        const int j = 32 * g + lane;
        const float2* wr = reinterpret_cast<const float2*>(w_hh + j * 32);
#pragma unroll
        for (int q = 0; q < 16; q++) {
            float2 t = __ldg(wr + q);
            w[g][q] = pk2(t.x * sc, t.y * sc);
        }
        wih[g]  = w_ih[j] * sc;
        bias[g] = (b_ih[j] + b_hh[j]) * sc;
    }

    for (;;) {
        int task = 0;
        if (lane == 0) task = atomicAdd(&g_next, 1);
        task = __shfl_sync(0xffffffffu, task, 0);
        if (task >= B_) break;

        const int b   = g_order[task];
        const int len = lengths[b];
        const float* xp = x + (long)b * T_;

        float c = 0.0f;
        hs[0][wrp][lane] = 0.0f;
        hs[1][wrp][lane] = 0.0f;
        __syncwarp();

        float xt = __ldg(xp + (len - 1));
        int pb = 0;

        for (int t = len - 1; t >= 0; --t) {
            float xn = (t > 0) ? __ldg(xp + t - 1) : 0.0f;   // prefetch

            const ulonglong2* hp =
                reinterpret_cast<const ulonglong2*>(hs[pb][wrp]);

            ull a0 = pk2(fmaf(xt, wih[0], bias[0]), 0.0f);
            ull a1 = pk2(fmaf(xt, wih[1], bias[1]), 0.0f);
            ull a2 = pk2(fmaf(xt, wih[2], bias[2]), 0.0f);
            ull a3 = pk2(fmaf(xt, wih[3], bias[3]), 0.0f);

#pragma unroll
            for (int q = 0; q < 8; q++) {
                ulonglong2 h2 = hp[q];                 // broadcast LDS.128
                a0 = ffma2(h2.x, w[0][2 * q],     a0);
                a0 = ffma2(h2.y, w[0][2 * q + 1], a0);
                a1 = ffma2(h2.x, w[1][2 * q],     a1);
                a1 = ffma2(h2.y, w[1][2 * q + 1], a1);
                a2 = ffma2(h2.x, w[2][2 * q],     a2);
                a2 = ffma2(h2.y, w[2][2 * q + 1], a2);
                a3 = ffma2(h2.x, w[3][2 * q],     a3);
                a3 = ffma2(h2.y, w[3][2 * q + 1], a3);
            }
            float2 s0 = unpk(a0), s1 = unpk(a1), s2 = unpk(a2), s3 = unpk(a3);
            float iv = sig_pre(s0.x + s0.y);
            float fv = sig_pre(s1.x + s1.y);
            float gv = tanh_pre(s2.x + s2.y);
            float ov = sig_pre(s3.x + s3.y);
            c = fmaf(fv, c, iv * gv);
            float h = ov * tanh_pre(2.0f * LOG2E * c);

            pb ^= 1;
            hs[pb][wrp][lane] = h;
            __syncwarp();
            xt = xn;
        }

        // ---- MLP head ----
        const float* hf = hs[pb][wrp];
        float y0 = fc_b[lane];
        float y1 = fc_b[lane + 32];
#pragma unroll
        for (int k = 0; k < 32; k++) {
            float hk = hf[k];
            y0 = fmaf(hk, __ldg(fc_w + lane * 32 + k),        y0);
            y1 = fmaf(hk, __ldg(fc_w + (lane + 32) * 32 + k), y1);
        }
        float e0 = (y0 > 0.0f) ? y0 : (ex2a(LOG2E * y0) - 1.0f);
        float e1 = (y1 > 0.0f) ? y1 : (ex2a(LOG2E * y1) - 1.0f);
        float p  = fmaf(e0, __ldg(fc2_w + lane),
                        e1 * __ldg(fc2_w + lane + 32));
#pragma unroll
        for (int off = 16; off; off >>= 1)
            p += __shfl_xor_sync(0xffffffffu, p, off);
        if (lane == 0) out[b] = sig_f(p + fc2_b[0]);
        __syncwarp();   // protect hs reuse by next task
    }
}

// ---------------- launch ----------------
extern "C" void kernel_launch(void* const* d_in, const int* in_sizes, int n_in,
                              void* d_out, int out_size)
{
    const float* x       = (const float*)d_in[0];
    const int*   lengths = (const int*)  d_in[1];
    const float* w_ih    = (const float*)d_in[2];
    const float* w_hh    = (const float*)d_in[3];
    const float* b_ih    = (const float*)d_in[4];
    const float* b_hh    = (const float*)d_in[5];
    const float* fc_w    = (const float*)d_in[6];
    const float* fc_b    = (const float*)d_in[7];
    const float* fc2_w   = (const float*)d_in[8];
    const float* fc2_b   = (const float*)d_in[9];
    float* out = (float*)d_out;

    k_zero<<<2, 1024>>>();
    k_hist<<<B_ / 256, 256>>>(lengths);
    k_scan<<<1, 1024>>>();
    k_scatter<<<B_ / 256, 256>>>(lengths);
    k_lstm<<<148, 256>>>(x, lengths, w_ih, w_hh, b_ih, b_hh,
                         fc_w, fc_b, fc2_w, fc2_b, out);
}

// round 4
// speedup vs baseline: 3.3791x; 1.0221x over previous
#include <cuda_runtime.h>
#include <cstdint>

#define B_  4096
#define T_  2048
#define HH  32
#define NGRP (B_ / 2)
typedef unsigned long long ull;

// ---------------- device globals ----------------
__device__ int g_next;
__device__ int g_cnt[T_];
__device__ int g_order[B_];

// ---------------- helpers ----------------
__device__ __forceinline__ ull ffma2(ull a, ull b, ull c) {
    ull d;
    asm("fma.rn.f32x2 %0, %1, %2, %3;" : "=l"(d) : "l"(a), "l"(b), "l"(c));
    return d;
}
__device__ __forceinline__ ull pk2(float lo, float hi) {
    ull r;
    asm("mov.b64 %0, {%1, %2};" : "=l"(r) : "f"(lo), "f"(hi));
    return r;
}
__device__ __forceinline__ float2 unpk(ull v) {
    float2 r;
    asm("mov.b64 {%0, %1}, %2;" : "=f"(r.x), "=f"(r.y) : "l"(v));
    return r;
}
__device__ __forceinline__ float ex2a(float x) {
    float r; asm("ex2.approx.f32 %0, %1;" : "=f"(r) : "f"(x)); return r;
}
__device__ __forceinline__ float rcpa(float x) {
    float r; asm("rcp.approx.f32 %0, %1;" : "=f"(r) : "f"(x)); return r;
}
#define LOG2E 1.4426950408889634f
__device__ __forceinline__ float sig_pre(float xs)  { return rcpa(1.0f + ex2a(xs)); }
__device__ __forceinline__ float tanh_pre(float xs) { return fmaf(-2.0f, rcpa(1.0f + ex2a(xs)), 1.0f); }
__device__ __forceinline__ float sig_f(float x)     { return rcpa(1.0f + ex2a(-LOG2E * x)); }

// ---------------- counting sort by descending length ----------------
__global__ void k_zero() {
    int i = blockIdx.x * blockDim.x + threadIdx.x;
    if (i < T_) g_cnt[i] = 0;
    if (i == 0) g_next = 0;
}
__global__ void k_hist(const int* __restrict__ lengths) {
    int b = blockIdx.x * blockDim.x + threadIdx.x;
    if (b < B_) atomicAdd(&g_cnt[T_ - lengths[b]], 1);
}
__global__ void k_scan() {
    __shared__ int ps[1024];
    int tid = threadIdx.x;
    int a = g_cnt[2 * tid], b = g_cnt[2 * tid + 1];
    int s = a + b;
    ps[tid] = s;
    __syncthreads();
    for (int d = 1; d < 1024; d <<= 1) {
        int v = (tid >= d) ? ps[tid - d] : 0;
        __syncthreads();
        ps[tid] += v;
        __syncthreads();
    }
    int incl = ps[tid];
    int excl = incl - s;
    g_cnt[2 * tid]     = excl;
    g_cnt[2 * tid + 1] = excl + a;
}
__global__ void k_scatter(const int* __restrict__ lengths) {
    int b = blockIdx.x * blockDim.x + threadIdx.x;
    if (b < B_) {
        int pos = atomicAdd(&g_cnt[T_ - lengths[b]], 1);
        g_order[pos] = b;
    }
}

// ---------------- main kernel: one warp == TWO sequences ----------------
// lane l owns h/c element l of both sequences; gate rows {l,32+l,64+l,96+l}.
// All recurrent weights in registers (64 packed f32x2), pre-scaled:
// i/f/o rows by -LOG2E, g row by +2*LOG2E. Smem carries only the two
// 32-float h vectors (double-buffered).
__global__ __launch_bounds__(128, 2) void k_lstm(
    const float* __restrict__ x,      const int*   __restrict__ lengths,
    const float* __restrict__ w_ih,   const float* __restrict__ w_hh,
    const float* __restrict__ b_ih,   const float* __restrict__ b_hh,
    const float* __restrict__ fc_w,   const float* __restrict__ fc_b,
    const float* __restrict__ fc2_w,  const float* __restrict__ fc2_b,
    float* __restrict__ out)
{
    __shared__ __align__(16) float hs[2][4][2][HH];   // [buf][warp][seq][elem]

    const int lane = threadIdx.x & 31;
    const int wrp  = threadIdx.x >> 5;

    // ---- recurrent weights -> registers (pre-scaled) ----
    ull w0[16], w1[16], w2[16], w3[16];
    float wih[4], bias[4];
    {
        const float2* r0 = reinterpret_cast<const float2*>(w_hh + (     lane) * 32);
        const float2* r1 = reinterpret_cast<const float2*>(w_hh + (32 + lane) * 32);
        const float2* r2 = reinterpret_cast<const float2*>(w_hh + (64 + lane) * 32);
        const float2* r3 = reinterpret_cast<const float2*>(w_hh + (96 + lane) * 32);
#pragma unroll
        for (int q = 0; q < 16; q++) {
            float2 t;
            t = __ldg(r0 + q); w0[q] = pk2(t.x * -LOG2E,        t.y * -LOG2E);
            t = __ldg(r1 + q); w1[q] = pk2(t.x * -LOG2E,        t.y * -LOG2E);
            t = __ldg(r2 + q); w2[q] = pk2(t.x * (2.0f * LOG2E), t.y * (2.0f * LOG2E));
            t = __ldg(r3 + q); w3[q] = pk2(t.x * -LOG2E,        t.y * -LOG2E);
        }
#pragma unroll
        for (int g = 0; g < 4; g++) {
            const float sc = (g == 2) ? (2.0f * LOG2E) : (-LOG2E);
            const int j = 32 * g + lane;
            wih[g]  = w_ih[j] * sc;
            bias[g] = (b_ih[j] + b_hh[j]) * sc;
        }
    }

    for (;;) {
        int task = 0;
        if (lane == 0) task = atomicAdd(&g_next, 1);
        task = __shfl_sync(0xffffffffu, task, 0);
        if (task >= NGRP) break;

        const int sidA = g_order[2 * task];
        const int sidB = g_order[2 * task + 1];
        const int lenA = lengths[sidA];
        const int lenB = lengths[sidB];          // lenB <= lenA (desc sort)
        const float* xpA = x + (long)sidA * T_;
        const float* xpB = x + (long)sidB * T_;

        float cA = 0.0f, cB = 0.0f, hAo = 0.0f, hBo = 0.0f;
        hs[0][wrp][0][lane] = 0.0f; hs[0][wrp][1][lane] = 0.0f;
        hs[1][wrp][0][lane] = 0.0f; hs[1][wrp][1][lane] = 0.0f;
        __syncwarp();

        float xtA = __ldg(xpA + lenA - 1);
        float xtB = __ldg(xpB + lenB - 1);
        int pb = 0;

        for (int k = 0; k < lenA; ++k) {
            int ixA = lenA - 2 - k, ixB = lenB - 2 - k;
            float xnA = (ixA >= 0) ? __ldg(xpA + ixA) : 0.0f;
            float xnB = (ixB >= 0) ? __ldg(xpB + ixB) : 0.0f;

            const ulonglong2* hpA = reinterpret_cast<const ulonglong2*>(hs[pb][wrp][0]);
            const ulonglong2* hpB = reinterpret_cast<const ulonglong2*>(hs[pb][wrp][1]);

            ull a0A = pk2(fmaf(xtA, wih[0], bias[0]), 0.0f);
            ull a1A = pk2(fmaf(xtA, wih[1], bias[1]), 0.0f);
            ull a2A = pk2(fmaf(xtA, wih[2], bias[2]), 0.0f);
            ull a3A = pk2(fmaf(xtA, wih[3], bias[3]), 0.0f);
            ull a0B = pk2(fmaf(xtB, wih[0], bias[0]), 0.0f);
            ull a1B = pk2(fmaf(xtB, wih[1], bias[1]), 0.0f);
            ull a2B = pk2(fmaf(xtB, wih[2], bias[2]), 0.0f);
            ull a3B = pk2(fmaf(xtB, wih[3], bias[3]), 0.0f);

#pragma unroll
            for (int q = 0; q < 8; q++) {
                ulonglong2 hA = hpA[q];              // broadcast LDS.128
                ulonglong2 hB = hpB[q];
                a0A = ffma2(hA.x, w0[2 * q], a0A); a0A = ffma2(hA.y, w0[2 * q + 1], a0A);
                a1A = ffma2(hA.x, w1[2 * q], a1A); a1A = ffma2(hA.y, w1[2 * q + 1], a1A);
                a2A = ffma2(hA.x, w2[2 * q], a2A); a2A = ffma2(hA.y, w2[2 * q + 1], a2A);
                a3A = ffma2(hA.x, w3[2 * q], a3A); a3A = ffma2(hA.y, w3[2 * q + 1], a3A);
                a0B = ffma2(hB.x, w0[2 * q], a0B); a0B = ffma2(hB.y, w0[2 * q + 1], a0B);
                a1B = ffma2(hB.x, w1[2 * q], a1B); a1B = ffma2(hB.y, w1[2 * q + 1], a1B);
                a2B = ffma2(hB.x, w2[2 * q], a2B); a2B = ffma2(hB.y, w2[2 * q + 1], a2B);
                a3B = ffma2(hB.x, w3[2 * q], a3B); a3B = ffma2(hB.y, w3[2 * q + 1], a3B);
            }

            const int npb = pb ^ 1;
            {
                float2 s0 = unpk(a0A), s1 = unpk(a1A), s2 = unpk(a2A), s3 = unpk(a3A);
                float iv = sig_pre(s0.x + s0.y);
                float fv = sig_pre(s1.x + s1.y);
                float gv = tanh_pre(s2.x + s2.y);
                float ov = sig_pre(s3.x + s3.y);
                float cn = fmaf(fv, cA, iv * gv);
                float hn = ov * tanh_pre(2.0f * LOG2E * cn);
                cA = cn; hAo = hn;                    // k < lenA always
                hs[npb][wrp][0][lane] = hAo;
            }
            {
                float2 s0 = unpk(a0B), s1 = unpk(a1B), s2 = unpk(a2B), s3 = unpk(a3B);
                float iv = sig_pre(s0.x + s0.y);
                float fv = sig_pre(s1.x + s1.y);
                float gv = tanh_pre(s2.x + s2.y);
                float ov = sig_pre(s3.x + s3.y);
                float cn = fmaf(fv, cB, iv * gv);
                float hn = ov * tanh_pre(2.0f * LOG2E * cn);
                if (k < lenB) { cB = cn; hBo = hn; }  // freeze finished seq
                hs[npb][wrp][1][lane] = hBo;
            }
            pb = npb;
            __syncwarp();
            xtA = xnA; xtB = xnB;
        }

        // ---- MLP head for the 2 sequences ----
#pragma unroll 1
        for (int s = 0; s < 2; s++) {
            const float* hf = hs[pb][wrp][s];
            float y0 = fc_b[lane];
            float y1 = fc_b[lane + 32];
#pragma unroll
            for (int kk = 0; kk < 32; kk++) {
                float hk = hf[kk];
                y0 = fmaf(hk, __ldg(fc_w + lane * 32 + kk),        y0);
                y1 = fmaf(hk, __ldg(fc_w + (lane + 32) * 32 + kk), y1);
            }
            float e0 = (y0 > 0.0f) ? y0 : (ex2a(LOG2E * y0) - 1.0f);
            float e1 = (y1 > 0.0f) ? y1 : (ex2a(LOG2E * y1) - 1.0f);
            float p  = fmaf(e0, __ldg(fc2_w + lane),
                            e1 * __ldg(fc2_w + lane + 32));
#pragma unroll
            for (int off = 16; off; off >>= 1)
                p += __shfl_xor_sync(0xffffffffu, p, off);
            if (lane == 0) out[(s == 0) ? sidA : sidB] = sig_f(p + fc2_b[0]);
        }
        __syncwarp();
    }
}

// ---------------- launch ----------------
extern "C" void kernel_launch(void* const* d_in, const int* in_sizes, int n_in,
                              void* d_out, int out_size)
{
    const float* x       = (const float*)d_in[0];
    const int*   lengths = (const int*)  d_in[1];
    const float* w_ih    = (const float*)d_in[2];
    const float* w_hh    = (const float*)d_in[3];
    const float* b_ih    = (const float*)d_in[4];
    const float* b_hh    = (const float*)d_in[5];
    const float* fc_w    = (const float*)d_in[6];
    const float* fc_b    = (const float*)d_in[7];
    const float* fc2_w   = (const float*)d_in[8];
    const float* fc2_b   = (const float*)d_in[9];
    float* out = (float*)d_out;

    k_zero<<<2, 1024>>>();
    k_hist<<<B_ / 256, 256>>>(lengths);
    k_scan<<<1, 1024>>>();
    k_scatter<<<B_ / 256, 256>>>(lengths);
    k_lstm<<<148 * 2, 128>>>(x, lengths, w_ih, w_hh, b_ih, b_hh,
                             fc_w, fc_b, fc2_w, fc2_b, out);
}

// round 5
// speedup vs baseline: 3.5313x; 1.0451x over previous
#include <cuda_runtime.h>
#include <cstdint>

#define B_  4096
#define T_  2048
#define HH  32
typedef unsigned long long ull;

// ---------------- device globals ----------------
__device__ int g_next;
__device__ int g_order[B_];

// ---------------- helpers ----------------
__device__ __forceinline__ ull ffma2(ull a, ull b, ull c) {
    ull d;
    asm("fma.rn.f32x2 %0, %1, %2, %3;" : "=l"(d) : "l"(a), "l"(b), "l"(c));
    return d;
}
__device__ __forceinline__ ull pk2(float lo, float hi) {
    ull r;
    asm("mov.b64 %0, {%1, %2};" : "=l"(r) : "f"(lo), "f"(hi));
    return r;
}
__device__ __forceinline__ float2 unpk(ull v) {
    float2 r;
    asm("mov.b64 {%0, %1}, %2;" : "=f"(r.x), "=f"(r.y) : "l"(v));
    return r;
}
__device__ __forceinline__ float ex2a(float x) {
    float r; asm("ex2.approx.f32 %0, %1;" : "=f"(r) : "f"(x)); return r;
}
__device__ __forceinline__ float rcpa(float x) {
    float r; asm("rcp.approx.f32 %0, %1;" : "=f"(r) : "f"(x)); return r;
}
#define LOG2E 1.4426950408889634f
__device__ __forceinline__ float sig_pre(float xs)  { return rcpa(1.0f + ex2a(xs)); }
__device__ __forceinline__ float tanh_pre(float xs) { return fmaf(-2.0f, rcpa(1.0f + ex2a(xs)), 1.0f); }
__device__ __forceinline__ float sig_f(float x)     { return rcpa(1.0f + ex2a(-LOG2E * x)); }

// ---------------- single-block counting sort (desc length) + queue reset ----
__global__ void k_sort(const int* __restrict__ lengths) {
    __shared__ int cnt[T_];
    __shared__ int ps[1024];
    const int tid = threadIdx.x;

    cnt[tid] = 0;
    cnt[tid + 1024] = 0;
    if (tid == 0) g_next = 0;
    __syncthreads();

    for (int b = tid; b < B_; b += 1024)
        atomicAdd(&cnt[T_ - lengths[b]], 1);
    __syncthreads();

    int a = cnt[2 * tid], bb = cnt[2 * tid + 1];
    int s = a + bb;
    ps[tid] = s;
    __syncthreads();
    for (int d = 1; d < 1024; d <<= 1) {
        int v = (tid >= d) ? ps[tid - d] : 0;
        __syncthreads();
        ps[tid] += v;
        __syncthreads();
    }
    int excl = ps[tid] - s;
    cnt[2 * tid]     = excl;
    cnt[2 * tid + 1] = excl + a;
    __syncthreads();

    for (int b = tid; b < B_; b += 1024) {
        int pos = atomicAdd(&cnt[T_ - lengths[b]], 1);
        g_order[pos] = b;
    }
}

// ---------------- main kernel: one warp == one sequence, 3 warps/SMSP ------
// lane l owns h/c element l and gate rows {l,32+l,64+l,96+l}. All recurrent
// weights in registers (64 packed f32x2), pre-scaled (i/f/o by -LOG2E,
// g by 2*LOG2E). Smem carries only the double-buffered 32-float h vector.
__global__ __launch_bounds__(128, 3) void k_lstm(
    const float* __restrict__ x,      const int*   __restrict__ lengths,
    const float* __restrict__ w_ih,   const float* __restrict__ w_hh,
    const float* __restrict__ b_ih,   const float* __restrict__ b_hh,
    const float* __restrict__ fc_w,   const float* __restrict__ fc_b,
    const float* __restrict__ fc2_w,  const float* __restrict__ fc2_b,
    float* __restrict__ out)
{
    __shared__ __align__(16) float hs[2][4][HH];    // [buf][warp][elem]

    const int lane = threadIdx.x & 31;
    const int wrp  = threadIdx.x >> 5;

    // ---- recurrent weights -> registers (pre-scaled) ----
    ull w0[16], w1[16], w2[16], w3[16];
    float wih[4], bias[4];
    {
        const float2* r0 = reinterpret_cast<const float2*>(w_hh + (     lane) * 32);
        const float2* r1 = reinterpret_cast<const float2*>(w_hh + (32 + lane) * 32);
        const float2* r2 = reinterpret_cast<const float2*>(w_hh + (64 + lane) * 32);
        const float2* r3 = reinterpret_cast<const float2*>(w_hh + (96 + lane) * 32);
#pragma unroll
        for (int q = 0; q < 16; q++) {
            float2 t;
            t = __ldg(r0 + q); w0[q] = pk2(t.x * -LOG2E,         t.y * -LOG2E);
            t = __ldg(r1 + q); w1[q] = pk2(t.x * -LOG2E,         t.y * -LOG2E);
            t = __ldg(r2 + q); w2[q] = pk2(t.x * (2.0f * LOG2E), t.y * (2.0f * LOG2E));
            t = __ldg(r3 + q); w3[q] = pk2(t.x * -LOG2E,         t.y * -LOG2E);
        }
#pragma unroll
        for (int g = 0; g < 4; g++) {
            const float sc = (g == 2) ? (2.0f * LOG2E) : (-LOG2E);
            const int j = 32 * g + lane;
            wih[g]  = w_ih[j] * sc;
            bias[g] = (b_ih[j] + b_hh[j]) * sc;
        }
    }

    for (;;) {
        int task = 0;
        if (lane == 0) task = atomicAdd(&g_next, 1);
        task = __shfl_sync(0xffffffffu, task, 0);
        if (task >= B_) break;

        const int b   = g_order[task];
        const int len = lengths[b];
        const float* xp = x + (long)b * T_;

        float c = 0.0f;
        hs[0][wrp][lane] = 0.0f;
        hs[1][wrp][lane] = 0.0f;
        __syncwarp();

        float xt = __ldg(xp + (len - 1));
        int pb = 0;

        for (int t = len - 1; t >= 0; --t) {
            float xn = (t > 0) ? __ldg(xp + t - 1) : 0.0f;   // prefetch

            const ulonglong2* hp =
                reinterpret_cast<const ulonglong2*>(hs[pb][wrp]);

            // split accumulators: two depth-8 chains per gate
            ull a0 = pk2(fmaf(xt, wih[0], bias[0]), 0.0f), a0b = pk2(0.0f, 0.0f);
            ull a1 = pk2(fmaf(xt, wih[1], bias[1]), 0.0f), a1b = pk2(0.0f, 0.0f);
            ull a2 = pk2(fmaf(xt, wih[2], bias[2]), 0.0f), a2b = pk2(0.0f, 0.0f);
            ull a3 = pk2(fmaf(xt, wih[3], bias[3]), 0.0f), a3b = pk2(0.0f, 0.0f);

#pragma unroll
            for (int q = 0; q < 8; q++) {
                ulonglong2 h2 = hp[q];                 // broadcast LDS.128
                a0  = ffma2(h2.x, w0[2 * q],     a0);
                a0b = ffma2(h2.y, w0[2 * q + 1], a0b);
                a1  = ffma2(h2.x, w1[2 * q],     a1);
                a1b = ffma2(h2.y, w1[2 * q + 1], a1b);
                a2  = ffma2(h2.x, w2[2 * q],     a2);
                a2b = ffma2(h2.y, w2[2 * q + 1], a2b);
                a3  = ffma2(h2.x, w3[2 * q],     a3);
                a3b = ffma2(h2.y, w3[2 * q + 1], a3b);
            }
            float2 s0 = unpk(a0), s0b = unpk(a0b);
            float2 s1 = unpk(a1), s1b = unpk(a1b);
            float2 s2 = unpk(a2), s2b = unpk(a2b);
            float2 s3 = unpk(a3), s3b = unpk(a3b);
            float gi = (s0.x + s0b.x) + (s0.y + s0b.y);
            float gf = (s1.x + s1b.x) + (s1.y + s1b.y);
            float gg = (s2.x + s2b.x) + (s2.y + s2b.y);
            float go = (s3.x + s3b.x) + (s3.y + s3b.y);

            float iv = sig_pre(gi);
            float fv = sig_pre(gf);
            float gv = tanh_pre(gg);
            float ov = sig_pre(go);
            c = fmaf(fv, c, iv * gv);
            float h = ov * tanh_pre(2.0f * LOG2E * c);

            pb ^= 1;
            hs[pb][wrp][lane] = h;
            __syncwarp();
            xt = xn;
        }

        // ---- MLP head ----
        const float* hf = hs[pb][wrp];
        float y0 = fc_b[lane];
        float y1 = fc_b[lane + 32];
#pragma unroll
        for (int k = 0; k < 32; k++) {
            float hk = hf[k];
            y0 = fmaf(hk, __ldg(fc_w + lane * 32 + k),        y0);
            y1 = fmaf(hk, __ldg(fc_w + (lane + 32) * 32 + k), y1);
        }
        float e0 = (y0 > 0.0f) ? y0 : (ex2a(LOG2E * y0) - 1.0f);
        float e1 = (y1 > 0.0f) ? y1 : (ex2a(LOG2E * y1) - 1.0f);
        float p  = fmaf(e0, __ldg(fc2_w + lane),
                        e1 * __ldg(fc2_w + lane + 32));
#pragma unroll
        for (int off = 16; off; off >>= 1)
            p += __shfl_xor_sync(0xffffffffu, p, off);
        if (lane == 0) out[b] = sig_f(p + fc2_b[0]);
        __syncwarp();   // protect hs reuse by next task
    }
}

// ---------------- launch (2 launches -> ncu -s 5 -c 1 captures k_lstm) -----
extern "C" void kernel_launch(void* const* d_in, const int* in_sizes, int n_in,
                              void* d_out, int out_size)
{
    const float* x       = (const float*)d_in[0];
    const int*   lengths = (const int*)  d_in[1];
    const float* w_ih    = (const float*)d_in[2];
    const float* w_hh    = (const float*)d_in[3];
    const float* b_ih    = (const float*)d_in[4];
    const float* b_hh    = (const float*)d_in[5];
    const float* fc_w    = (const float*)d_in[6];
    const float* fc_b    = (const float*)d_in[7];
    const float* fc2_w   = (const float*)d_in[8];
    const float* fc2_b   = (const float*)d_in[9];
    float* out = (float*)d_out;

    k_sort<<<1, 1024>>>(lengths);
    k_lstm<<<148 * 3, 128>>>(x, lengths, w_ih, w_hh, b_ih, b_hh,
                             fc_w, fc_b, fc2_w, fc2_b, out);
}

// round 8
// speedup vs baseline: 4.2570x; 1.2055x over previous
#include <cuda_runtime.h>
#include <cstdint>

#define B_  4096
#define T_  2048
#define HH  32
typedef unsigned long long ull;

// ---------------- device globals ----------------
__device__ int g_next;
__device__ int g_order[B_];

// ---------------- helpers ----------------
__device__ __forceinline__ ull ffma2(ull a, ull b, ull c) {
    ull d;
    asm("fma.rn.f32x2 %0, %1, %2, %3;" : "=l"(d) : "l"(a), "l"(b), "l"(c));
    return d;
}
__device__ __forceinline__ ull add2(ull a, ull b) {
    ull d;
    asm("add.rn.f32x2 %0, %1, %2;" : "=l"(d) : "l"(a), "l"(b));
    return d;
}
__device__ __forceinline__ ull pk2(float lo, float hi) {
    ull r;
    asm("mov.b64 %0, {%1, %2};" : "=l"(r) : "f"(lo), "f"(hi));
    return r;
}
__device__ __forceinline__ float2 unpk(ull v) {
    float2 r;
    asm("mov.b64 {%0, %1}, %2;" : "=f"(r.x), "=f"(r.y) : "l"(v));
    return r;
}
__device__ __forceinline__ float ex2a(float x) {
    float r; asm("ex2.approx.f32 %0, %1;" : "=f"(r) : "f"(x)); return r;
}
__device__ __forceinline__ float tanha(float x) {
    float r; asm("tanh.approx.f32 %0, %1;" : "=f"(r) : "f"(x)); return r;
}
#define LOG2E 1.4426950408889634f

// ---------------- single-block counting sort (desc length) + queue reset ----
__global__ void k_sort(const int* __restrict__ lengths) {
    __shared__ int cnt[T_];
    __shared__ int ps[1024];
    const int tid = threadIdx.x;

    cnt[tid] = 0;
    cnt[tid + 1024] = 0;
    if (tid == 0) g_next = 0;
    __syncthreads();

    for (int b = tid; b < B_; b += 1024)
        atomicAdd(&cnt[T_ - lengths[b]], 1);
    __syncthreads();

    int a = cnt[2 * tid], bb = cnt[2 * tid + 1];
    int s = a + bb;
    ps[tid] = s;
    __syncthreads();
    for (int d = 1; d < 1024; d <<= 1) {
        int v = (tid >= d) ? ps[tid - d] : 0;
        __syncthreads();
        ps[tid] += v;
        __syncthreads();
    }
    int excl = ps[tid] - s;
    cnt[2 * tid]     = excl;
    cnt[2 * tid + 1] = excl + a;
    __syncthreads();

    for (int b = tid; b < B_; b += 1024) {
        int pos = atomicAdd(&cnt[T_ - lengths[b]], 1);
        g_order[pos] = b;
    }
}

// one LSTM step on gate accumulators -> updates c, writes h to hs[pb^1]
// i/f/o weights pre-scaled by 0.5 (sigmoid = 0.5*tanh(x/2)+0.5); g row raw.
#define LSTM_STEP(XT)                                                         \
    do {                                                                      \
        const ulonglong2* hp =                                                \
            reinterpret_cast<const ulonglong2*>(hs[pb][wrp]);                 \
        ull xp2 = pk2((XT), (XT));                                            \
        ull a0 = ffma2(xp2, wihp[0], biasp[0]), a0b = zero2;                  \
        ull a1 = ffma2(xp2, wihp[1], biasp[1]), a1b = zero2;                  \
        ull a2 = ffma2(xp2, wihp[2], biasp[2]), a2b = zero2;                  \
        ull a3 = ffma2(xp2, wihp[3], biasp[3]), a3b = zero2;                  \
        _Pragma("unroll")                                                     \
        for (int q = 0; q < 8; q++) {                                         \
            ulonglong2 h2 = hp[q];                                            \
            a0  = ffma2(h2.x, w0[2 * q],     a0);                             \
            a0b = ffma2(h2.y, w0[2 * q + 1], a0b);                            \
            a1  = ffma2(h2.x, w1[2 * q],     a1);                             \
            a1b = ffma2(h2.y, w1[2 * q + 1], a1b);                            \
            a2  = ffma2(h2.x, w2[2 * q],     a2);                             \
            a2b = ffma2(h2.y, w2[2 * q + 1], a2b);                            \
            a3  = ffma2(h2.x, w3[2 * q],     a3);                             \
            a3b = ffma2(h2.y, w3[2 * q + 1], a3b);                            \
        }                                                                     \
        float2 f0 = unpk(add2(a0, a0b));                                      \
        float2 f1 = unpk(add2(a1, a1b));                                      \
        float2 f2 = unpk(add2(a2, a2b));                                      \
        float2 f3 = unpk(add2(a3, a3b));                                      \
        float iv = fmaf(tanha(f0.x + f0.y), 0.5f, 0.5f);                      \
        float fv = fmaf(tanha(f1.x + f1.y), 0.5f, 0.5f);                      \
        float gv = tanha(f2.x + f2.y);                                        \
        float ov = fmaf(tanha(f3.x + f3.y), 0.5f, 0.5f);                      \
        c = fmaf(fv, c, iv * gv);                                             \
        float h = ov * tanha(c);                                              \
        pb ^= 1;                                                              \
        hs[pb][wrp][lane] = h;                                                \
        __syncwarp();                                                         \
    } while (0)

// ---------------- main kernel: one warp == one sequence, 3 warps/SMSP ------
__global__ __launch_bounds__(128, 3) void k_lstm(
    const float* __restrict__ x,      const int*   __restrict__ lengths,
    const float* __restrict__ w_ih,   const float* __restrict__ w_hh,
    const float* __restrict__ b_ih,   const float* __restrict__ b_hh,
    const float* __restrict__ fc_w,   const float* __restrict__ fc_b,
    const float* __restrict__ fc2_w,  const float* __restrict__ fc2_b,
    float* __restrict__ out)
{
    __shared__ __align__(16) float hs[2][4][HH];    // [buf][warp][elem]

    const int lane = threadIdx.x & 31;
    const int wrp  = threadIdx.x >> 5;
    const ull zero2 = pk2(0.0f, 0.0f);

    // ---- recurrent weights -> registers; i/f/o scaled 0.5, g raw ----
    ull w0[16], w1[16], w2[16], w3[16];
    ull wihp[4], biasp[4];
    {
        const float2* r0 = reinterpret_cast<const float2*>(w_hh + (     lane) * 32);
        const float2* r1 = reinterpret_cast<const float2*>(w_hh + (32 + lane) * 32);
        const float2* r2 = reinterpret_cast<const float2*>(w_hh + (64 + lane) * 32);
        const float2* r3 = reinterpret_cast<const float2*>(w_hh + (96 + lane) * 32);
#pragma unroll
        for (int q = 0; q < 16; q++) {
            float2 t;
            t = __ldg(r0 + q); w0[q] = pk2(t.x * 0.5f, t.y * 0.5f);
            t = __ldg(r1 + q); w1[q] = pk2(t.x * 0.5f, t.y * 0.5f);
            t = __ldg(r2 + q); w2[q] = pk2(t.x,        t.y);
            t = __ldg(r3 + q); w3[q] = pk2(t.x * 0.5f, t.y * 0.5f);
        }
#pragma unroll
        for (int g = 0; g < 4; g++) {
            const float sc = (g == 2) ? 1.0f : 0.5f;
            const int j = 32 * g + lane;
            wihp[g]  = pk2(w_ih[j] * sc, 0.0f);
            biasp[g] = pk2((b_ih[j] + b_hh[j]) * sc, 0.0f);
        }
    }

    for (;;) {
        int task = 0;
        if (lane == 0) task = atomicAdd(&g_next, 1);
        task = __shfl_sync(0xffffffffu, task, 0);
        if (task >= B_) break;

        const int b   = g_order[task];
        const int len = lengths[b];
        const float* xp = x + (long)b * T_;

        float c = 0.0f;
        hs[0][wrp][lane] = 0.0f;
        hs[1][wrp][lane] = 0.0f;
        __syncwarp();

        float xt = __ldg(xp + (len - 1));
        int pb = 0;

        // main loop: unconditional prefetch (t goes len-1 .. 1)
        for (int t = len - 1; t > 0; --t) {
            float xn = __ldg(xp + t - 1);
            LSTM_STEP(xt);
            xt = xn;
        }
        // peeled final step (t == 0)
        LSTM_STEP(xt);

        // ---- MLP head ----
        const float* hf = hs[pb][wrp];
        float y0 = fc_b[lane];
        float y1 = fc_b[lane + 32];
#pragma unroll
        for (int k = 0; k < 32; k++) {
            float hk = hf[k];
            y0 = fmaf(hk, __ldg(fc_w + lane * 32 + k),        y0);
            y1 = fmaf(hk, __ldg(fc_w + (lane + 32) * 32 + k), y1);
        }
        float e0 = (y0 > 0.0f) ? y0 : (ex2a(LOG2E * y0) - 1.0f);
        float e1 = (y1 > 0.0f) ? y1 : (ex2a(LOG2E * y1) - 1.0f);
        float p  = fmaf(e0, __ldg(fc2_w + lane),
                        e1 * __ldg(fc2_w + lane + 32));
#pragma unroll
        for (int off = 16; off; off >>= 1)
            p += __shfl_xor_sync(0xffffffffu, p, off);
        if (lane == 0)
            out[b] = fmaf(tanha(0.5f * (p + fc2_b[0])), 0.5f, 0.5f);
        __syncwarp();   // protect hs reuse by next task
    }
}

// ---------------- launch ----------------
extern "C" void kernel_launch(void* const* d_in, const int* in_sizes, int n_in,
                              void* d_out, int out_size)
{
    const float* x       = (const float*)d_in[0];
    const int*   lengths = (const int*)  d_in[1];
    const float* w_ih    = (const float*)d_in[2];
    const float* w_hh    = (const float*)d_in[3];
    const float* b_ih    = (const float*)d_in[4];
    const float* b_hh    = (const float*)d_in[5];
    const float* fc_w    = (const float*)d_in[6];
    const float* fc_b    = (const float*)d_in[7];
    const float* fc2_w   = (const float*)d_in[8];
    const float* fc2_b   = (const float*)d_in[9];
    float* out = (float*)d_out;

    k_sort<<<1, 1024>>>(lengths);
    k_lstm<<<148 * 3, 128>>>(x, lengths, w_ih, w_hh, b_ih, b_hh,
                             fc_w, fc_b, fc2_w, fc2_b, out);
}